// round 1
// baseline (speedup 1.0000x reference)
#include <cuda_runtime.h>
#include <cstddef>

// Problem shape assumptions (verified against dataset): H=512, I=1, NAV=1.
// B and T derived from in_sizes at launch.
#define HDIM  512
#define TPB   128      // threads per block in RNN kernels
#define RPT   4        // h-values per thread (TPB*RPT == HDIM)
#define NWARP (TPB/32)
#define TWO_PI_F 6.283185307179586476925286766559f

// flag: 1 if W_h is exactly the identity matrix
__device__ int g_identity;

// per-(t,b,warp) partial output sums (float2 = {p0,p1})
// capacity: (T+1)*B*NWARP = 1025*256*4 = 1,049,600 slots; 4M gives headroom.
__device__ __align__(16) float2 g_part[4u * 1024u * 1024u];

__global__ void set_flag_kernel() { g_identity = 1; }

__global__ void check_identity_kernel(const float* __restrict__ W_h, int n) {
    int i = blockIdx.x * blockDim.x + threadIdx.x;
    if (i < n) {
        int r = i / HDIM;
        int c = i - r * HDIM;
        float e = (r == c) ? 1.0f : 0.0f;
        if (W_h[i] != e) g_identity = 0;   // benign race: only writes 0
    }
}

// ---------------------------------------------------------------------------
// Fast path: W_h == I  =>  h_t[h] = relu(h_{t-1}[h] + x_t*W_x[h] + b_x[h])
// One block per batch element. Thread owns RPT h-indices in registers.
// Emits per-warp partial <h_t, W_out[0]>, <h_t, W_out[1]> each step; no
// block-level barriers in the hot loop.
// ---------------------------------------------------------------------------
__global__ void __launch_bounds__(TPB) rnn_fast_kernel(
    const float* __restrict__ x,       // [B, T]  (I==1)
    const float* __restrict__ theta0,  // [B]
    const float* __restrict__ W_x,     // [H]
    const float* __restrict__ b_x,     // [H]
    const float* __restrict__ W_h0,    // [H]
    const float* __restrict__ b_h0,    // [H]
    const float* __restrict__ W_out,   // [2, H]
    int B, int T)
{
    if (!g_identity) return;

    extern __shared__ float sx[];      // x[b, 0..T)
    const int b    = blockIdx.x;
    const int tid  = threadIdx.x;
    const int lane = tid & 31;
    const int warp = tid >> 5;

    for (int t = tid; t < T; t += TPB) sx[t] = x[(size_t)b * T + t];

    float wx[RPT], bx[RPT], w0[RPT], w1[RPT], h[RPT];
    const float th = theta0[b] * TWO_PI_F;
    #pragma unroll
    for (int r = 0; r < RPT; r++) {
        const int hh = r * TPB + tid;
        wx[r] = W_x[hh];
        bx[r] = b_x[hh];
        w0[r] = W_out[hh];
        w1[r] = W_out[HDIM + hh];
        h[r]  = fmaf(th, W_h0[hh], b_h0[hh]);   // h0 (no relu, per reference)
    }
    __syncthreads();

    float2* part = g_part + (size_t)b * NWARP + warp;
    const size_t pstride = (size_t)B * NWARP;

    // t = 0 row (output head applied to h0)
    {
        float p0 = 0.f, p1 = 0.f;
        #pragma unroll
        for (int r = 0; r < RPT; r++) {
            p0 = fmaf(h[r], w0[r], p0);
            p1 = fmaf(h[r], w1[r], p1);
        }
        #pragma unroll
        for (int o = 16; o; o >>= 1) {
            p0 += __shfl_xor_sync(0xffffffffu, p0, o);
            p1 += __shfl_xor_sync(0xffffffffu, p1, o);
        }
        if (lane == 0) *part = make_float2(p0, p1);
    }

    #pragma unroll 4
    for (int t = 0; t < T; t++) {
        const float xt = sx[t];
        float p0 = 0.f, p1 = 0.f;
        #pragma unroll
        for (int r = 0; r < RPT; r++) {
            const float c = fmaf(xt, wx[r], bx[r]);
            h[r] = fmaxf(h[r] + c, 0.f);
            p0 = fmaf(h[r], w0[r], p0);
            p1 = fmaf(h[r], w1[r], p1);
        }
        #pragma unroll
        for (int o = 16; o; o >>= 1) {
            p0 += __shfl_xor_sync(0xffffffffu, p0, o);
            p1 += __shfl_xor_sync(0xffffffffu, p1, o);
        }
        part += pstride;
        if (lane == 0) *part = make_float2(p0, p1);
    }
}

// ---------------------------------------------------------------------------
// General fallback: arbitrary W_h. One block per batch; h kept in smem,
// full [H x H] matvec per step. Correct but slow; only runs if W_h != I.
// ---------------------------------------------------------------------------
__global__ void __launch_bounds__(TPB) rnn_general_kernel(
    const float* __restrict__ x,
    const float* __restrict__ theta0,
    const float* __restrict__ W_h,     // [H, H]
    const float* __restrict__ W_x,
    const float* __restrict__ b_x,
    const float* __restrict__ W_h0,
    const float* __restrict__ b_h0,
    const float* __restrict__ W_out,
    int B, int T)
{
    if (g_identity) return;

    __shared__ float hbuf[2][HDIM];
    const int b    = blockIdx.x;
    const int tid  = threadIdx.x;
    const int lane = tid & 31;
    const int warp = tid >> 5;

    float wx[RPT], bx[RPT], w0[RPT], w1[RPT], hr[RPT];
    const float th = theta0[b] * TWO_PI_F;
    #pragma unroll
    for (int r = 0; r < RPT; r++) {
        const int hh = r * TPB + tid;
        wx[r] = W_x[hh];
        bx[r] = b_x[hh];
        w0[r] = W_out[hh];
        w1[r] = W_out[HDIM + hh];
        hr[r] = fmaf(th, W_h0[hh], b_h0[hh]);
        hbuf[0][hh] = hr[r];
    }
    __syncthreads();

    float2* part = g_part + (size_t)b * NWARP + warp;
    const size_t pstride = (size_t)B * NWARP;

    {   // t = 0 row
        float p0 = 0.f, p1 = 0.f;
        #pragma unroll
        for (int r = 0; r < RPT; r++) {
            p0 = fmaf(hr[r], w0[r], p0);
            p1 = fmaf(hr[r], w1[r], p1);
        }
        #pragma unroll
        for (int o = 16; o; o >>= 1) {
            p0 += __shfl_xor_sync(0xffffffffu, p0, o);
            p1 += __shfl_xor_sync(0xffffffffu, p1, o);
        }
        if (lane == 0) *part = make_float2(p0, p1);
    }

    int cur = 0;
    for (int t = 0; t < T; t++) {
        const float xt = x[(size_t)b * T + t];
        float acc[RPT];
        #pragma unroll
        for (int r = 0; r < RPT; r++) acc[r] = fmaf(xt, wx[r], bx[r]);

        const float* hs = hbuf[cur];
        for (int k = 0; k < HDIM; k++) {
            const float hk = hs[k];
            #pragma unroll
            for (int r = 0; r < RPT; r++)
                acc[r] = fmaf(W_h[(size_t)(r * TPB + tid) * HDIM + k], hk, acc[r]);
        }
        float p0 = 0.f, p1 = 0.f;
        #pragma unroll
        for (int r = 0; r < RPT; r++) {
            hr[r] = fmaxf(acc[r], 0.f);
            hbuf[1 - cur][r * TPB + tid] = hr[r];
            p0 = fmaf(hr[r], w0[r], p0);
            p1 = fmaf(hr[r], w1[r], p1);
        }
        #pragma unroll
        for (int o = 16; o; o >>= 1) {
            p0 += __shfl_xor_sync(0xffffffffu, p0, o);
            p1 += __shfl_xor_sync(0xffffffffu, p1, o);
        }
        part += pstride;
        if (lane == 0) *part = make_float2(p0, p1);
        __syncthreads();          // writes to hbuf[1-cur] visible before next read
        cur ^= 1;
    }
}

// ---------------------------------------------------------------------------
// Finalize: out[t,b,:] = sum over NWARP warp partials + b_out
// ---------------------------------------------------------------------------
__global__ void finalize_kernel(float* __restrict__ out,
                                const float* __restrict__ b_out,
                                int total /* (T+1)*B */)
{
    const int idx = blockIdx.x * blockDim.x + threadIdx.x;
    if (idx >= total) return;
    const float4* p = reinterpret_cast<const float4*>(g_part + (size_t)idx * NWARP);
    const float4 a = p[0];
    const float4 c = p[1];
    const float o0 = (a.x + a.z) + (c.x + c.z) + b_out[0];
    const float o1 = (a.y + a.w) + (c.y + c.w) + b_out[1];
    reinterpret_cast<float2*>(out)[idx] = make_float2(o0, o1);
}

extern "C" void kernel_launch(void* const* d_in, const int* in_sizes, int n_in,
                              void* d_out, int out_size)
{
    const float* x     = (const float*)d_in[0];
    const float* th0   = (const float*)d_in[1];
    const float* W_h   = (const float*)d_in[2];
    const float* W_x   = (const float*)d_in[3];
    const float* b_x   = (const float*)d_in[4];
    const float* W_h0  = (const float*)d_in[5];
    const float* b_h0  = (const float*)d_in[6];
    const float* W_out = (const float*)d_in[7];
    const float* b_out = (const float*)d_in[8];

    const int H   = in_sizes[4];          // 512
    const int NAV = in_sizes[8] / 2;      // 1
    const int B   = in_sizes[1] / NAV;    // 256
    const int I   = in_sizes[3] / H;      // 1
    const int T   = in_sizes[0] / (B * I);// 1024

    set_flag_kernel<<<1, 1>>>();
    const int n = H * H;
    check_identity_kernel<<<(n + 255) / 256, 256>>>(W_h, n);

    const size_t shmem = (size_t)T * sizeof(float);
    rnn_fast_kernel<<<B, TPB, shmem>>>(x, th0, W_x, b_x, W_h0, b_h0, W_out, B, T);
    rnn_general_kernel<<<B, TPB>>>(x, th0, W_h, W_x, b_x, W_h0, b_h0, W_out, B, T);

    const int total = (T + 1) * B;
    finalize_kernel<<<(total + 255) / 256, 256>>>((float*)d_out, b_out, total);
}

// round 3
// speedup vs baseline: 3.0651x; 3.0651x over previous
#include <cuda_runtime.h>
#include <cstddef>

#define HDIM  512
#define TDIM  1024
#define TPB   128
#define CH    (TDIM / TPB)    // 8 t-values per thread in scans
#define RPT   (HDIM / TPB)    // 4 h-values per thread (slow paths)
#define NWARP (TPB / 32)
#define TWO_PI_F 6.283185307179586476925286766559f
#define CINF  3.402823466e38f
#define FULLM 0xffffffffu

// Sticky violation flags: zero at module load; only ever written to 1.
__device__ int g_wh_not_identity;
__device__ int g_bx_nonzero;

// slow-path per-(t,b,warp) partials
__device__ __align__(16) float2 g_part[2u * 1024u * 1024u];

// ---------------------------------------------------------------------------
__device__ __forceinline__ float warp_sum(float v) {
    #pragma unroll
    for (int o = 16; o; o >>= 1) v += __shfl_xor_sync(FULLM, v, o);
    return v;
}

// ---------------------------------------------------------------------------
__global__ void check_kernel(const float* __restrict__ W_h,
                             const float* __restrict__ b_x, int H) {
    const int i = blockIdx.x * blockDim.x + threadIdx.x;
    const int n = H * H;
    if (i < n) {
        const int r = i / H;
        const int c = i - r * H;
        const float e = (r == c) ? 1.0f : 0.0f;
        if (W_h[i] != e) g_wh_not_identity = 1;
    }
    if (i < H && b_x[i] != 0.0f) g_bx_nonzero = 1;
}

// ---------------------------------------------------------------------------
// Main kernel. One block per batch element.
// Fast path (W_h==I, b_x==0, T==TDIM, H==HDIM):
//   h_t = X_t*wx - M_t,  M_t = min(a, wx*Cmin_t) [wx>=0] / min(a, wx*Cmax_t),
//   a = -h0. R_t = sum_h M_t*wk changes only at prefix-min/max record times.
//   out[t,b,k] = X_t*<wx,wk> - R_t[k] + b_out[k], written directly.
// ---------------------------------------------------------------------------
__global__ void __launch_bounds__(TPB) rnn_main_kernel(
    const float* __restrict__ x,       // [B, T]
    const float* __restrict__ theta0,  // [B]
    const float* __restrict__ W_h,     // [H, H]
    const float* __restrict__ W_x,     // [H]
    const float* __restrict__ b_x,     // [H]
    const float* __restrict__ W_h0,    // [H]
    const float* __restrict__ b_h0,    // [H]
    const float* __restrict__ W_out,   // [2, H]
    const float* __restrict__ b_out,   // [2]
    float* __restrict__ out,           // [T+1, B, 2]
    int B, int T, int fastOK)
{
    __shared__ float sX[TDIM + 1];
    __shared__ float sCmin[TDIM + 1];
    __shared__ float sCmax[TDIM + 1];
    __shared__ int   sSeg[TDIM + 1];
    __shared__ float sRecCmin[TDIM + 1];
    __shared__ float sRecCmax[TDIM + 1];
    __shared__ float2 sRrec[TDIM + 1];
    __shared__ float swx[HDIM], sa[HDIM], sw0[HDIM], sw1[HDIM];
    __shared__ float sScrA[NWARP], sScrB[NWARP];
    __shared__ int   sScrI[NWARP];
    __shared__ int   snrec;
    __shared__ float sDred[NWARP * 2];

    const int b    = blockIdx.x;
    const int tid  = threadIdx.x;
    const int lane = tid & 31;
    const int warp = tid >> 5;
    const int nid  = g_wh_not_identity;
    const int bxnz = g_bx_nonzero;
    const float th = theta0[b] * TWO_PI_F;

    if (!nid && !bxnz && fastOK) {
        // ================= FAST PATH =================
        // ---- Phase 1: X = cumsum(x) (block scan, add) ----
        const float* xb = x + (size_t)b * T;
        float lx[CH];
        {
            float run = 0.f;
            #pragma unroll
            for (int j = 0; j < CH; j++) { run += xb[tid * CH + j]; lx[j] = run; }
            float ws = run;
            #pragma unroll
            for (int o = 1; o < 32; o <<= 1) {
                float u = __shfl_up_sync(FULLM, ws, o);
                if (lane >= o) ws += u;
            }
            if (lane == 31) sScrA[warp] = ws;
            __syncthreads();
            float off = 0.f;
            for (int w = 0; w < warp; w++) off += sScrA[w];
            float lp = __shfl_up_sync(FULLM, ws, 1);
            if (lane > 0) off += lp;
            #pragma unroll
            for (int j = 0; j < CH; j++) lx[j] += off;
        }

        // ---- Phase 2: Cmin/Cmax = prefix min/max of X (block scan) ----
        {
            float vmin = CINF, vmax = -CINF;
            float lmn[CH], lmx[CH];
            #pragma unroll
            for (int j = 0; j < CH; j++) {
                vmin = fminf(vmin, lx[j]); lmn[j] = vmin;
                vmax = fmaxf(vmax, lx[j]); lmx[j] = vmax;
            }
            float wmn = vmin, wmx = vmax;
            #pragma unroll
            for (int o = 1; o < 32; o <<= 1) {
                float a0 = __shfl_up_sync(FULLM, wmn, o);
                float a1 = __shfl_up_sync(FULLM, wmx, o);
                if (lane >= o) { wmn = fminf(wmn, a0); wmx = fmaxf(wmx, a1); }
            }
            __syncthreads();                    // sScrA reuse safety
            if (lane == 31) { sScrA[warp] = wmn; sScrB[warp] = wmx; }
            __syncthreads();
            float omn = CINF, omx = -CINF;
            for (int w = 0; w < warp; w++) {
                omn = fminf(omn, sScrA[w]);
                omx = fmaxf(omx, sScrB[w]);
            }
            float pmn = __shfl_up_sync(FULLM, wmn, 1);
            float pmx = __shfl_up_sync(FULLM, wmx, 1);
            if (lane > 0) { omn = fminf(omn, pmn); omx = fmaxf(omx, pmx); }
            #pragma unroll
            for (int j = 0; j < CH; j++) {
                const int t = tid * CH + j + 1;
                sX[t]    = lx[j];
                sCmin[t] = fminf(lmn[j], omn);
                sCmax[t] = fmaxf(lmx[j], omx);
            }
            if (tid == 0) sX[0] = 0.f;
        }
        __syncthreads();

        // ---- Phase 3: segment ids (prefix count of record times) ----
        {
            int lc[CH];
            int c = 0;
            #pragma unroll
            for (int j = 0; j < CH; j++) {
                const int t = tid * CH + j + 1;
                const float pm = (t == 1) ?  CINF : sCmin[t - 1];
                const float pM = (t == 1) ? -CINF : sCmax[t - 1];
                const bool ch = (sCmin[t] < pm) || (sCmax[t] > pM);
                c += ch ? 1 : 0;
                lc[j] = c;
            }
            int wc = c;
            #pragma unroll
            for (int o = 1; o < 32; o <<= 1) {
                int u = __shfl_up_sync(FULLM, wc, o);
                if (lane >= o) wc += u;
            }
            if (lane == 31) sScrI[warp] = wc;
            __syncthreads();
            int off = 0;
            for (int w = 0; w < warp; w++) off += sScrI[w];
            int lp = __shfl_up_sync(FULLM, wc, 1);
            if (lane > 0) off += lp;
            #pragma unroll
            for (int j = 0; j < CH; j++) {
                const int t = tid * CH + j + 1;
                sSeg[t] = lc[j] + off;
            }
            if (tid == TPB - 1) snrec = lc[CH - 1] + off;
        }
        __syncthreads();

        // scatter record (Cmin, Cmax) values by record id
        #pragma unroll
        for (int j = 0; j < CH; j++) {
            const int t = tid * CH + j + 1;
            const float pm = (t == 1) ?  CINF : sCmin[t - 1];
            const float pM = (t == 1) ? -CINF : sCmax[t - 1];
            if ((sCmin[t] < pm) || (sCmax[t] > pM)) {
                const int rid = sSeg[t];
                sRecCmin[rid] = sCmin[t];
                sRecCmax[rid] = sCmax[t];
            }
        }

        // ---- Phase 4: stage per-h data ----
        for (int h = tid; h < HDIM; h += TPB) {
            swx[h] = W_x[h];
            sa[h]  = -fmaf(th, W_h0[h], b_h0[h]);   // a = -h0
            sw0[h] = W_out[h];
            sw1[h] = W_out[HDIM + h];
        }
        __syncthreads();

        // ---- Phase 5: R at each record (r=0 is the t=0 / init record) ----
        const int nrec = snrec;
        for (int r = warp; r <= nrec; r += NWARP) {
            float p0 = 0.f, p1 = 0.f;
            if (r == 0) {
                for (int h = lane; h < HDIM; h += 32) {
                    const float a = sa[h];
                    p0 = fmaf(a, sw0[h], p0);
                    p1 = fmaf(a, sw1[h], p1);
                }
            } else {
                const float cmin = sRecCmin[r];
                const float cmax = sRecCmax[r];
                for (int h = lane; h < HDIM; h += 32) {
                    const float wx = swx[h];
                    const float c  = (wx >= 0.f) ? cmin : cmax;
                    const float m  = fminf(sa[h], wx * c);
                    p0 = fmaf(m, sw0[h], p0);
                    p1 = fmaf(m, sw1[h], p1);
                }
            }
            p0 = warp_sum(p0);
            p1 = warp_sum(p1);
            if (lane == 0) sRrec[r] = make_float2(p0, p1);
        }

        // ---- Phase 6: dots D0 = <wx,w0>, D2 = <wx,w1> ----
        {
            float d0 = 0.f, d2 = 0.f;
            for (int h = tid; h < HDIM; h += TPB) {
                d0 = fmaf(swx[h], sw0[h], d0);
                d2 = fmaf(swx[h], sw1[h], d2);
            }
            d0 = warp_sum(d0);
            d2 = warp_sum(d2);
            if (lane == 0) { sDred[warp * 2] = d0; sDred[warp * 2 + 1] = d2; }
        }
        __syncthreads();

        float D0 = 0.f, D2 = 0.f;
        #pragma unroll
        for (int w = 0; w < NWARP; w++) { D0 += sDred[w * 2]; D2 += sDred[w * 2 + 1]; }
        const float b0 = b_out[0], b1 = b_out[1];

        // ---- Phase 7: emit outputs ----
        for (int t = tid; t <= T; t += TPB) {
            const int rid = (t == 0) ? 0 : sSeg[t];
            const float2 R = sRrec[rid];
            const float X = sX[t];
            float2 o;
            o.x = fmaf(X, D0, b0) - R.x;
            o.y = fmaf(X, D2, b1) - R.y;
            reinterpret_cast<float2*>(out)[(size_t)t * B + b] = o;
        }
        return;
    }

    // ================= SLOW PATHS (write warp partials to g_part) ========
    float2* part = g_part + (size_t)b * NWARP + warp;
    const size_t pstride = (size_t)B * NWARP;

    if (!nid) {
        // W_h == I: direct relu recurrence (any b_x, any T)
        float wx[RPT], bx[RPT], w0[RPT], w1[RPT], h[RPT];
        #pragma unroll
        for (int r = 0; r < RPT; r++) {
            const int hh = r * TPB + tid;
            wx[r] = W_x[hh];
            bx[r] = b_x[hh];
            w0[r] = W_out[hh];
            w1[r] = W_out[HDIM + hh];
            h[r]  = fmaf(th, W_h0[hh], b_h0[hh]);
        }
        {
            float p0 = 0.f, p1 = 0.f;
            #pragma unroll
            for (int r = 0; r < RPT; r++) {
                p0 = fmaf(h[r], w0[r], p0);
                p1 = fmaf(h[r], w1[r], p1);
            }
            p0 = warp_sum(p0); p1 = warp_sum(p1);
            if (lane == 0) *part = make_float2(p0, p1);
        }
        for (int t = 0; t < T; t++) {
            const float xt = __ldg(&x[(size_t)b * T + t]);
            float p0 = 0.f, p1 = 0.f;
            #pragma unroll
            for (int r = 0; r < RPT; r++) {
                const float c = fmaf(xt, wx[r], bx[r]);
                h[r] = fmaxf(h[r] + c, 0.f);
                p0 = fmaf(h[r], w0[r], p0);
                p1 = fmaf(h[r], w1[r], p1);
            }
            p0 = warp_sum(p0); p1 = warp_sum(p1);
            part += pstride;
            if (lane == 0) *part = make_float2(p0, p1);
        }
    } else {
        // General W_h: full matvec per step
        __shared__ float hbuf[2][HDIM];
        float wx[RPT], bx[RPT], w0[RPT], w1[RPT], hr[RPT];
        #pragma unroll
        for (int r = 0; r < RPT; r++) {
            const int hh = r * TPB + tid;
            wx[r] = W_x[hh];
            bx[r] = b_x[hh];
            w0[r] = W_out[hh];
            w1[r] = W_out[HDIM + hh];
            hr[r] = fmaf(th, W_h0[hh], b_h0[hh]);
            hbuf[0][hh] = hr[r];
        }
        __syncthreads();
        {
            float p0 = 0.f, p1 = 0.f;
            #pragma unroll
            for (int r = 0; r < RPT; r++) {
                p0 = fmaf(hr[r], w0[r], p0);
                p1 = fmaf(hr[r], w1[r], p1);
            }
            p0 = warp_sum(p0); p1 = warp_sum(p1);
            if (lane == 0) *part = make_float2(p0, p1);
        }
        int cur = 0;
        for (int t = 0; t < T; t++) {
            const float xt = __ldg(&x[(size_t)b * T + t]);
            float acc[RPT];
            #pragma unroll
            for (int r = 0; r < RPT; r++) acc[r] = fmaf(xt, wx[r], bx[r]);
            const float* hs = hbuf[cur];
            for (int k = 0; k < HDIM; k++) {
                const float hk = hs[k];
                #pragma unroll
                for (int r = 0; r < RPT; r++)
                    acc[r] = fmaf(W_h[(size_t)(r * TPB + tid) * HDIM + k], hk, acc[r]);
            }
            float p0 = 0.f, p1 = 0.f;
            #pragma unroll
            for (int r = 0; r < RPT; r++) {
                hr[r] = fmaxf(acc[r], 0.f);
                hbuf[1 - cur][r * TPB + tid] = hr[r];
                p0 = fmaf(hr[r], w0[r], p0);
                p1 = fmaf(hr[r], w1[r], p1);
            }
            p0 = warp_sum(p0); p1 = warp_sum(p1);
            part += pstride;
            if (lane == 0) *part = make_float2(p0, p1);
            __syncthreads();
            cur ^= 1;
        }
    }
}

// ---------------------------------------------------------------------------
// Finalize for slow paths only (fast path writes out directly).
// ---------------------------------------------------------------------------
__global__ void finalize_slow_kernel(float* __restrict__ out,
                                     const float* __restrict__ b_out,
                                     int total, int fastOK)
{
    if (fastOK && !g_wh_not_identity && !g_bx_nonzero) return;
    const int idx = blockIdx.x * blockDim.x + threadIdx.x;
    if (idx >= total) return;
    const float4* p = reinterpret_cast<const float4*>(g_part + (size_t)idx * NWARP);
    const float4 a = p[0];
    const float4 c = p[1];
    const float o0 = (a.x + a.z) + (c.x + c.z) + b_out[0];
    const float o1 = (a.y + a.w) + (c.y + c.w) + b_out[1];
    reinterpret_cast<float2*>(out)[idx] = make_float2(o0, o1);
}

// ---------------------------------------------------------------------------
extern "C" void kernel_launch(void* const* d_in, const int* in_sizes, int n_in,
                              void* d_out, int out_size)
{
    const float* x     = (const float*)d_in[0];
    const float* th0   = (const float*)d_in[1];
    const float* W_h   = (const float*)d_in[2];
    const float* b_x   = (const float*)d_in[4];
    const float* W_x   = (const float*)d_in[3];
    const float* W_h0  = (const float*)d_in[5];
    const float* b_h0  = (const float*)d_in[6];
    const float* W_out = (const float*)d_in[7];
    const float* b_out = (const float*)d_in[8];

    const int H   = in_sizes[4];           // 512
    const int NAV = in_sizes[8] / 2;       // 1
    const int B   = in_sizes[1] / NAV;     // 256
    const int I   = in_sizes[3] / H;       // 1
    const int T   = in_sizes[0] / (B * I); // 1024

    const int fastOK = (H == HDIM && T == TDIM) ? 1 : 0;

    const int n = H * H;
    check_kernel<<<(n + 255) / 256, 256>>>(W_h, b_x, H);

    rnn_main_kernel<<<B, TPB>>>(x, th0, W_h, W_x, b_x, W_h0, b_h0,
                                W_out, b_out, (float*)d_out, B, T, fastOK);

    const int total = (T + 1) * B;
    finalize_slow_kernel<<<(total + 255) / 256, 256>>>((float*)d_out, b_out,
                                                       total, fastOK);
}

// round 4
// speedup vs baseline: 5.7173x; 1.8653x over previous
#include <cuda_runtime.h>
#include <cstddef>

#define HDIM  512
#define TDIM  1024
#define TPB2  256            // main kernel threads
#define NW2   (TPB2 / 32)    // 8 warps
#define CH2   (TDIM / TPB2)  // 4 t-values per thread in scans
#define TPBS  128            // slow kernel threads
#define RPT   (HDIM / TPBS)  // 4
#define NWS   (TPBS / 32)
#define TWO_PI_F 6.283185307179586476925286766559f
#define CINF  3.402823466e38f
#define FULLM 0xffffffffu

// Sticky violation flags: zero at module load; only ever written to 1.
__device__ int g_wh_not_identity;
__device__ int g_bx_nonzero;

__device__ __forceinline__ float warp_sum(float v) {
    #pragma unroll
    for (int o = 16; o; o >>= 1) v += __shfl_xor_sync(FULLM, v, o);
    return v;
}

// ---------------------------------------------------------------------------
// Main kernel: one block per batch element. Also performs the W_h / b_x
// checks (distributed across all blocks). Fast path computed speculatively;
// fallback kernel overwrites out if a check tripped.
//
// Fast math: h_t = X_t*wx - M_t with M_t = min(a, wx*Cmin_t) for wx>=0 and
// min(a, wx*Cmax_t) for wx<0, a = -h0. R_t = sum_h M_t*wk changes only at
// prefix-min/max record times of the cumsum X. out = X_t*<wx,wk> - R + b.
// ---------------------------------------------------------------------------
__global__ void __launch_bounds__(TPB2) rnn_fast_kernel(
    const float* __restrict__ x,       // [B, T]
    const float* __restrict__ theta0,  // [B]
    const float* __restrict__ W_h,     // [H, H]
    const float* __restrict__ W_x,     // [H]
    const float* __restrict__ b_x,     // [H]
    const float* __restrict__ W_h0,    // [H]
    const float* __restrict__ b_h0,    // [H]
    const float* __restrict__ W_out,   // [2, H]
    const float* __restrict__ b_out,   // [2]
    float* __restrict__ out,           // [T+1, B, 2]
    int B, int T, int H, int fastOK)
{
    __shared__ float sX[TDIM + 1];
    __shared__ float sCmin[TDIM + 1];
    __shared__ float sCmax[TDIM + 1];
    __shared__ int   sSeg[TDIM + 1];
    __shared__ float sRecCmin[TDIM + 1];
    __shared__ float sRecCmax[TDIM + 1];
    __shared__ float2 sRrec[TDIM + 1];
    __shared__ float swx[HDIM], sa[HDIM], sw0[HDIM], sw1[HDIM];
    __shared__ float sScrA[NW2], sScrB[NW2];
    __shared__ int   sScrI[NW2];
    __shared__ int   snrec;
    __shared__ float sDred[NW2 * 2];

    const int b    = blockIdx.x;
    const int tid  = threadIdx.x;
    const int lane = tid & 31;
    const int warp = tid >> 5;
    const float INF = __int_as_float(0x7f800000);

    // ---- Distributed identity / zero checks (writes sticky flags) ----
    {
        const int n  = H * H;
        const int n4 = n >> 2;
        const float4* W4 = reinterpret_cast<const float4*>(W_h);
        for (int i4 = b * TPB2 + tid; i4 < n4; i4 += gridDim.x * TPB2) {
            const float4 v = W4[i4];
            const int e = i4 << 2;
            const int r = e / H;
            const int c = e - r * H;          // H%4==0 -> same row for all 4
            const float e0 = (c     == r) ? 1.f : 0.f;
            const float e1 = (c + 1 == r) ? 1.f : 0.f;
            const float e2 = (c + 2 == r) ? 1.f : 0.f;
            const float e3 = (c + 3 == r) ? 1.f : 0.f;
            if (v.x != e0 || v.y != e1 || v.z != e2 || v.w != e3)
                g_wh_not_identity = 1;
        }
        if (b == 0) {
            for (int i = (n4 << 2) + tid; i < n; i += TPB2) {  // tail (H%4!=0)
                const int r = i / H, c = i - r * H;
                if (W_h[i] != ((r == c) ? 1.f : 0.f)) g_wh_not_identity = 1;
            }
            for (int i = tid; i < H; i += TPB2)
                if (b_x[i] != 0.0f) g_bx_nonzero = 1;
        }
    }

    if (!fastOK) return;   // fallback kernel will do everything

    const float th = theta0[b] * TWO_PI_F;

    // ---- Phase 1: X = cumsum(x) (block scan) ----
    const float* xb = x + (size_t)b * TDIM;
    float lx[CH2];
    {
        const float4 v = reinterpret_cast<const float4*>(xb)[tid];
        lx[0] = v.x;
        lx[1] = v.x + v.y;
        lx[2] = lx[1] + v.z;
        lx[3] = lx[2] + v.w;
        float ws = lx[3];
        #pragma unroll
        for (int o = 1; o < 32; o <<= 1) {
            const float u = __shfl_up_sync(FULLM, ws, o);
            if (lane >= o) ws += u;
        }
        if (lane == 31) sScrA[warp] = ws;
        __syncthreads();
        float off = 0.f;
        for (int w = 0; w < warp; w++) off += sScrA[w];
        const float lp = __shfl_up_sync(FULLM, ws, 1);
        if (lane > 0) off += lp;
        #pragma unroll
        for (int j = 0; j < CH2; j++) lx[j] += off;
    }

    // ---- Phase 2: Cmin/Cmax = prefix min/max of X ----
    {
        float lmn[CH2], lmx[CH2];
        float vmin = CINF, vmax = -CINF;
        #pragma unroll
        for (int j = 0; j < CH2; j++) {
            vmin = fminf(vmin, lx[j]); lmn[j] = vmin;
            vmax = fmaxf(vmax, lx[j]); lmx[j] = vmax;
        }
        float wmn = vmin, wmx = vmax;
        #pragma unroll
        for (int o = 1; o < 32; o <<= 1) {
            const float a0 = __shfl_up_sync(FULLM, wmn, o);
            const float a1 = __shfl_up_sync(FULLM, wmx, o);
            if (lane >= o) { wmn = fminf(wmn, a0); wmx = fmaxf(wmx, a1); }
        }
        __syncthreads();                 // sScrA reuse
        if (lane == 31) { sScrA[warp] = wmn; sScrB[warp] = wmx; }
        __syncthreads();
        float omn = CINF, omx = -CINF;
        for (int w = 0; w < warp; w++) {
            omn = fminf(omn, sScrA[w]);
            omx = fmaxf(omx, sScrB[w]);
        }
        const float pmn = __shfl_up_sync(FULLM, wmn, 1);
        const float pmx = __shfl_up_sync(FULLM, wmx, 1);
        if (lane > 0) { omn = fminf(omn, pmn); omx = fmaxf(omx, pmx); }
        #pragma unroll
        for (int j = 0; j < CH2; j++) {
            const int t = tid * CH2 + j + 1;
            sX[t]    = lx[j];
            sCmin[t] = fminf(lmn[j], omn);
            sCmax[t] = fmaxf(lmx[j], omx);
        }
        if (tid == 0) sX[0] = 0.f;
    }
    __syncthreads();

    // ---- Phase 3: record-time segment ids (prefix count) ----
    {
        int lc[CH2];
        int c = 0;
        #pragma unroll
        for (int j = 0; j < CH2; j++) {
            const int t = tid * CH2 + j + 1;
            const float pm = (t == 1) ?  CINF : sCmin[t - 1];
            const float pM = (t == 1) ? -CINF : sCmax[t - 1];
            c += ((sCmin[t] < pm) || (sCmax[t] > pM)) ? 1 : 0;
            lc[j] = c;
        }
        int wc = c;
        #pragma unroll
        for (int o = 1; o < 32; o <<= 1) {
            const int u = __shfl_up_sync(FULLM, wc, o);
            if (lane >= o) wc += u;
        }
        if (lane == 31) sScrI[warp] = wc;
        __syncthreads();
        int off = 0;
        for (int w = 0; w < warp; w++) off += sScrI[w];
        const int lp = __shfl_up_sync(FULLM, wc, 1);
        if (lane > 0) off += lp;
        #pragma unroll
        for (int j = 0; j < CH2; j++)
            sSeg[tid * CH2 + j + 1] = lc[j] + off;
        if (tid == TPB2 - 1) snrec = lc[CH2 - 1] + off;
    }
    __syncthreads();

    // scatter record (Cmin, Cmax); record 0 = t=0 sentinel (INF trick)
    #pragma unroll
    for (int j = 0; j < CH2; j++) {
        const int t = tid * CH2 + j + 1;
        const float pm = (t == 1) ?  CINF : sCmin[t - 1];
        const float pM = (t == 1) ? -CINF : sCmax[t - 1];
        if ((sCmin[t] < pm) || (sCmax[t] > pM)) {
            const int rid = sSeg[t];
            sRecCmin[rid] = sCmin[t];
            sRecCmax[rid] = sCmax[t];
        }
    }
    if (tid == 0) {
        sRecCmin[0] = INF;     // min(a, wx*INF) == a  (NaN-safe for wx==0)
        sRecCmax[0] = -INF;
        sSeg[0] = 0;
    }

    // ---- Phase 4: stage per-h data ----
    #pragma unroll
    for (int r = 0; r < HDIM / TPB2; r++) {
        const int h = r * TPB2 + tid;
        swx[h] = W_x[h];
        sa[h]  = -fmaf(th, W_h0[h], b_h0[h]);   // a = -h0
        sw0[h] = W_out[h];
        sw1[h] = W_out[HDIM + h];
    }
    __syncthreads();

    // ---- Phase 5: R at each record (two records per warp iteration) ----
    const int nrec = snrec;
    for (int r = warp; r <= nrec; r += 2 * NW2) {
        const int  r2  = r + NW2;
        const bool h2  = (r2 <= nrec);
        const float cm0 = sRecCmin[r],  cx0 = sRecCmax[r];
        const float cm1 = h2 ? sRecCmin[r2] : 0.f;
        const float cx1 = h2 ? sRecCmax[r2] : 0.f;
        float p00 = 0.f, p01 = 0.f, p10 = 0.f, p11 = 0.f;
        #pragma unroll
        for (int i = 0; i < HDIM / 32; i++) {
            const int h = i * 32 + lane;
            const float wx = swx[h], a = sa[h];
            const float w0 = sw0[h], w1 = sw1[h];
            const float m0 = fminf(a, wx * ((wx >= 0.f) ? cm0 : cx0));
            p00 = fmaf(m0, w0, p00);
            p01 = fmaf(m0, w1, p01);
            const float m1 = fminf(a, wx * ((wx >= 0.f) ? cm1 : cx1));
            p10 = fmaf(m1, w0, p10);
            p11 = fmaf(m1, w1, p11);
        }
        #pragma unroll
        for (int o = 16; o; o >>= 1) {
            p00 += __shfl_xor_sync(FULLM, p00, o);
            p01 += __shfl_xor_sync(FULLM, p01, o);
            p10 += __shfl_xor_sync(FULLM, p10, o);
            p11 += __shfl_xor_sync(FULLM, p11, o);
        }
        if (lane == 0) {
            sRrec[r] = make_float2(p00, p01);
            if (h2) sRrec[r2] = make_float2(p10, p11);
        }
    }

    // ---- Phase 6: dots <wx,w0>, <wx,w1> ----
    {
        float d0 = 0.f, d2 = 0.f;
        #pragma unroll
        for (int r = 0; r < HDIM / TPB2; r++) {
            const int h = r * TPB2 + tid;
            d0 = fmaf(swx[h], sw0[h], d0);
            d2 = fmaf(swx[h], sw1[h], d2);
        }
        d0 = warp_sum(d0);
        d2 = warp_sum(d2);
        if (lane == 0) { sDred[warp * 2] = d0; sDred[warp * 2 + 1] = d2; }
    }
    __syncthreads();

    float D0 = 0.f, D2 = 0.f;
    #pragma unroll
    for (int w = 0; w < NW2; w++) { D0 += sDred[w * 2]; D2 += sDred[w * 2 + 1]; }
    const float b0 = b_out[0], b1 = b_out[1];

    // ---- Phase 7: emit outputs ----
    for (int t = tid; t <= TDIM; t += TPB2) {
        const float2 R = sRrec[sSeg[t]];
        const float  X = sX[t];
        float2 o;
        o.x = fmaf(X, D0, b0) - R.x;
        o.y = fmaf(X, D2, b1) - R.y;
        reinterpret_cast<float2*>(out)[(size_t)t * B + b] = o;
    }
}

// ---------------------------------------------------------------------------
// Fallback: runs only if a guard tripped (or shapes unexpected). Computes the
// recurrence directly and writes out itself (block reduce per step).
// ---------------------------------------------------------------------------
__global__ void __launch_bounds__(TPBS) rnn_slow_kernel(
    const float* __restrict__ x,
    const float* __restrict__ theta0,
    const float* __restrict__ W_h,
    const float* __restrict__ W_x,
    const float* __restrict__ b_x,
    const float* __restrict__ W_h0,
    const float* __restrict__ b_h0,
    const float* __restrict__ W_out,
    const float* __restrict__ b_out,
    float* __restrict__ out,
    int B, int T, int fastOK)
{
    const int nid  = g_wh_not_identity;
    const int bxnz = g_bx_nonzero;
    if (fastOK && !nid && !bxnz) return;

    __shared__ float2 sred[NWS];
    __shared__ float hbuf[2][HDIM];

    const int b    = blockIdx.x;
    const int tid  = threadIdx.x;
    const int lane = tid & 31;
    const int warp = tid >> 5;
    const float th = theta0[b] * TWO_PI_F;
    const float b0 = b_out[0], b1 = b_out[1];

    float wx[RPT], bx[RPT], w0[RPT], w1[RPT], h[RPT];
    #pragma unroll
    for (int r = 0; r < RPT; r++) {
        const int hh = r * TPBS + tid;
        wx[r] = W_x[hh];
        bx[r] = b_x[hh];
        w0[r] = W_out[hh];
        w1[r] = W_out[HDIM + hh];
        h[r]  = fmaf(th, W_h0[hh], b_h0[hh]);
        hbuf[0][hh] = h[r];
    }
    __syncthreads();

    // t = 0 row
    {
        float p0 = 0.f, p1 = 0.f;
        #pragma unroll
        for (int r = 0; r < RPT; r++) {
            p0 = fmaf(h[r], w0[r], p0);
            p1 = fmaf(h[r], w1[r], p1);
        }
        p0 = warp_sum(p0); p1 = warp_sum(p1);
        if (lane == 0) sred[warp] = make_float2(p0, p1);
        __syncthreads();
        if (tid == 0) {
            float o0 = b0, o1 = b1;
            for (int w = 0; w < NWS; w++) { o0 += sred[w].x; o1 += sred[w].y; }
            reinterpret_cast<float2*>(out)[b] = make_float2(o0, o1);
        }
        __syncthreads();
    }

    int cur = 0;
    for (int t = 0; t < T; t++) {
        const float xt = __ldg(&x[(size_t)b * T + t]);
        float acc[RPT];
        #pragma unroll
        for (int r = 0; r < RPT; r++) acc[r] = fmaf(xt, wx[r], bx[r]);

        if (!nid) {
            #pragma unroll
            for (int r = 0; r < RPT; r++) acc[r] += h[r];
        } else {
            const float* hs = hbuf[cur];
            for (int k = 0; k < HDIM; k++) {
                const float hk = hs[k];
                #pragma unroll
                for (int r = 0; r < RPT; r++)
                    acc[r] = fmaf(W_h[(size_t)(r * TPBS + tid) * HDIM + k], hk, acc[r]);
            }
        }
        float p0 = 0.f, p1 = 0.f;
        #pragma unroll
        for (int r = 0; r < RPT; r++) {
            h[r] = fmaxf(acc[r], 0.f);
            if (nid) hbuf[1 - cur][r * TPBS + tid] = h[r];
            p0 = fmaf(h[r], w0[r], p0);
            p1 = fmaf(h[r], w1[r], p1);
        }
        p0 = warp_sum(p0); p1 = warp_sum(p1);
        if (lane == 0) sred[warp] = make_float2(p0, p1);
        __syncthreads();
        if (tid == 0) {
            float o0 = b0, o1 = b1;
            for (int w = 0; w < NWS; w++) { o0 += sred[w].x; o1 += sred[w].y; }
            reinterpret_cast<float2*>(out)[(size_t)(t + 1) * B + b] = make_float2(o0, o1);
        }
        __syncthreads();
        cur ^= 1;
    }
}

// ---------------------------------------------------------------------------
extern "C" void kernel_launch(void* const* d_in, const int* in_sizes, int n_in,
                              void* d_out, int out_size)
{
    const float* x     = (const float*)d_in[0];
    const float* th0   = (const float*)d_in[1];
    const float* W_h   = (const float*)d_in[2];
    const float* W_x   = (const float*)d_in[3];
    const float* b_x   = (const float*)d_in[4];
    const float* W_h0  = (const float*)d_in[5];
    const float* b_h0  = (const float*)d_in[6];
    const float* W_out = (const float*)d_in[7];
    const float* b_out = (const float*)d_in[8];

    const int H   = in_sizes[4];           // 512
    const int NAV = in_sizes[8] / 2;       // 1
    const int B   = in_sizes[1] / NAV;     // 256
    const int I   = in_sizes[3] / H;       // 1
    const int T   = in_sizes[0] / (B * I); // 1024

    const int fastOK = (H == HDIM && T == TDIM) ? 1 : 0;

    rnn_fast_kernel<<<B, TPB2>>>(x, th0, W_h, W_x, b_x, W_h0, b_h0,
                                 W_out, b_out, (float*)d_out, B, T, H, fastOK);

    rnn_slow_kernel<<<B, TPBS>>>(x, th0, W_h, W_x, b_x, W_h0, b_h0,
                                 W_out, b_out, (float*)d_out, B, T, fastOK);
}